// round 12
// baseline (speedup 1.0000x reference)
#include <cuda_runtime.h>
#include <math_constants.h>

// Shapes (fixed): x: [B=32, C=256, H=128, W=128] float32
#define B_   32
#define C_   256
#define HW_  16384   // 128*128
#define HW4_ 4096    // HW/4 (float4 groups)

#define NPROD 64     // producer CTAs (4 channels each)
#define NCONS 64     // consumer CTAs (4 teams x 16 slices)
#define NCTA  (NPROD + NCONS)   // 128 <= 148 SMs: all co-resident
#define CAPB  2      // producer lead: live L2 set ~ (2+4)*16MB = 96MB < 126MB

#define ENTRO_BLOCKS 64
#define HIST_BLOCKS  64

// Scratch (device globals — no allocation allowed)
__device__ float g_pooled[B_ * C_];     // 32 KB
__device__ float g_ep[4][HW_];          // per-team entro partial sums, 256 KB
__device__ float g_ssum[NCONS];         // sigmoid partial per consumer CTA
__device__ float g_entro[HW_];          // 64 KB
__device__ float g_mm[ENTRO_BLOCKS * 2];// per-block (min,max)
__device__ int   g_hist[256];
__device__ int   g_cnt;
__device__ int   g_done[B_];            // producers finished batch b (count)
__device__ int   g_cons[B_];            // consumers finished batch b (count)

// ---------------------------------------------------------------------------
// K0: zero all flags/histogram for this graph replay
// ---------------------------------------------------------------------------
__global__ void k_init() {
    g_hist[threadIdx.x] = 0;
    if (threadIdx.x < B_) {
        g_done[threadIdx.x] = 0;
        g_cons[threadIdx.x] = 0;
    }
    if (threadIdx.x == 0) g_cnt = 0;
}

// ---------------------------------------------------------------------------
// K1 (fused, producer/consumer pipelined):
//  CTAs 0..63  (producers): pool 4 channels of batch b (DRAM), publish pooled,
//              release g_done[b]. Back-pressure via g_cons[b-CAPB].
//  CTAs 64..127 (consumers): team tm=q&3 takes batches tm,tm+4,..; slice q>>2
//              owns 256 float4 columns. Acquire g_done[b], read the L2-hot
//              batch (__ldcg), accumulate xn partials in registers; write raw
//              team-private partials to g_ep[tm].
//  All float reductions fixed-order -> deterministic.
// ---------------------------------------------------------------------------
__global__ void __launch_bounds__(512, 1) k_fused(const float* __restrict__ x) {
    const int cta = blockIdx.x;
    const int tid = threadIdx.x;
    const int w   = tid >> 5;
    const int l   = tid & 31;
    const float4* __restrict__ x4 = reinterpret_cast<const float4*>(x);

    if (cta < NPROD) {
        // ----------------------------- producer -----------------------------
        __shared__ float sprod[16];
        const int ch_local = w >> 2;     // 0..3
        const int quarter  = w & 3;      // 0..3
        const int ch = cta * 4 + ch_local;

        for (int b = 0; b < B_; b++) {
            if (b >= CAPB) {
                if (tid == 0)
                    while (atomicAdd(&g_cons[b - CAPB], 0) < 16) __nanosleep(200);
                __syncthreads();
            }
            const float4* __restrict__ p4 =
                x4 + (size_t)(b * C_ + ch) * HW4_ + quarter * 1024 + l;
            float s = 0.0f;
#pragma unroll 16
            for (int i = 0; i < 32; i++) {
                float4 v = p4[i * 32];
                s += (v.x + v.y) + (v.z + v.w);
            }
#pragma unroll
            for (int o = 16; o > 0; o >>= 1)
                s += __shfl_down_sync(0xffffffffu, s, o);
            if (l == 0) sprod[w] = s;
            __syncthreads();
            if (tid < 4) {
                float t = ((sprod[tid * 4 + 0] + sprod[tid * 4 + 1])
                         + (sprod[tid * 4 + 2] + sprod[tid * 4 + 3]));
                g_pooled[b * C_ + cta * 4 + tid] = t * (1.0f / (float)HW_);
            }
            __syncthreads();
            if (tid == 0) {
                __threadfence();                 // release pooled writes
                atomicAdd(&g_done[b], 1);
            }
        }
    } else {
        // ----------------------------- consumer -----------------------------
        const int q  = cta - NPROD;
        const int tm = q & 3;                    // team: batches tm, tm+4, ...
        const int sl = q >> 2;                   // slice: 256 columns
        const int colb = sl * 256 + w * 16 + (l >> 1); // float4 column in image
        const int half = l & 1;                  // channel half (128 each)

        __shared__ float spw[C_];
        __shared__ float swsg[16];

        float4 entro = make_float4(0.f, 0.f, 0.f, 0.f);
        float sig = 0.0f;

        for (int k = 0; k < 8; k++) {
            const int b = tm + 4 * k;
            if (tid == 0) {
                while (atomicAdd(&g_done[b], 0) < NPROD) __nanosleep(200);
                __threadfence();                 // acquire pooled writes
            }
            __syncthreads();
            if (tid < C_) spw[tid] = g_pooled[b * C_ + tid];
            __syncthreads();

            const float4* __restrict__ p4 =
                x4 + ((size_t)(b * C_) + half * 128) * HW4_ + colb;
            const float* pw = &spw[half * 128];
            float ax = 0.f, ay = 0.f, az = 0.f, aw = 0.f;
#pragma unroll 8
            for (int c = 0; c < 128; c++) {
                float4 v = __ldcg(&p4[(size_t)c * HW4_]);
                float wt = pw[c];
                ax = fmaf(v.x, wt, ax);
                ay = fmaf(v.y, wt, ay);
                az = fmaf(v.z, wt, az);
                aw = fmaf(v.w, wt, aw);
            }
            // combine channel halves within lane pair (even lane owns column)
            ax += __shfl_down_sync(0xffffffffu, ax, 1);
            ay += __shfl_down_sync(0xffffffffu, ay, 1);
            az += __shfl_down_sync(0xffffffffu, az, 1);
            aw += __shfl_down_sync(0xffffffffu, aw, 1);
            if (half == 0) {
                const float inv = 1.0f / (float)C_;
                float xx = ax * inv, xy = ay * inv, xz = az * inv, xw = aw * inv;
                entro.x += xx; entro.y += xy; entro.z += xz; entro.w += xw;
                sig += 1.0f / (1.0f + __expf(-xx))
                     + 1.0f / (1.0f + __expf(-xy))
                     + 1.0f / (1.0f + __expf(-xz))
                     + 1.0f / (1.0f + __expf(-xw));
            }
            __syncthreads();
            if (tid == 0) atomicAdd(&g_cons[b], 1);   // release L2 window
        }

        // write team-private raw partial sums (NO cross-team race)
        if (half == 0)
            reinterpret_cast<float4*>(g_ep[tm])[colb] = entro;

        // per-CTA sigmoid partial
#pragma unroll
        for (int o = 16; o > 0; o >>= 1)
            sig += __shfl_down_sync(0xffffffffu, sig, o);
        if (l == 0) swsg[w] = sig;
        __syncthreads();
        if (tid == 0) {
            float tsg = swsg[0];
#pragma unroll
            for (int i = 1; i < 16; i++) tsg += swsg[i];
            g_ssum[q] = tsg;
        }
    }
}

// ---------------------------------------------------------------------------
// K2: combine 4 team partials -> entro (mean over B), per-block min/max.
// ---------------------------------------------------------------------------
__global__ void __launch_bounds__(256) k_entrocomb() {
    const int sp = blockIdx.x * 256 + threadIdx.x;
    float v = (((g_ep[0][sp] + g_ep[1][sp]) + (g_ep[2][sp] + g_ep[3][sp])))
              * (1.0f / (float)B_);
    g_entro[sp] = v;

    __shared__ float smin[256], smax[256];
    smin[threadIdx.x] = v;
    smax[threadIdx.x] = v;
    __syncthreads();
#pragma unroll
    for (int o = 128; o > 0; o >>= 1) {
        if (threadIdx.x < o) {
            smin[threadIdx.x] = fminf(smin[threadIdx.x], smin[threadIdx.x + o]);
            smax[threadIdx.x] = fmaxf(smax[threadIdx.x], smax[threadIdx.x + o]);
        }
        __syncthreads();
    }
    if (threadIdx.x == 0) {
        g_mm[blockIdx.x * 2 + 0] = smin[0];
        g_mm[blockIdx.x * 2 + 1] = smax[0];
    }
}

// ---------------------------------------------------------------------------
// K3: 64 blocks: reduce min/max partials, bin 256 elements each into shared
//     histogram, flush to global. Last finished block computes the output.
// ---------------------------------------------------------------------------
__global__ void __launch_bounds__(256) k_histout(float* __restrict__ out) {
    const int tid = threadIdx.x;

    __shared__ float smin[64], smax[64];
    __shared__ int hist[256];
    hist[tid] = 0;
    if (tid < 64) {
        smin[tid] = g_mm[tid * 2 + 0];
        smax[tid] = g_mm[tid * 2 + 1];
    }
    __syncthreads();
#pragma unroll
    for (int o = 32; o > 0; o >>= 1) {
        if (tid < o) {
            smin[tid] = fminf(smin[tid], smin[tid + o]);
            smax[tid] = fmaxf(smax[tid], smax[tid + o]);
        }
        __syncthreads();
    }
    const float emin = smin[0];
    const float denom = smax[0] - emin;

    float e = (g_entro[blockIdx.x * 256 + tid] - emin) / denom * 255.0f;
    int bin = (int)floorf(e * (256.0f / 255.0f));
    bin = min(max(bin, 0), 255);
    atomicAdd(&hist[bin], 1);
    __syncthreads();

    if (hist[tid] != 0) atomicAdd(&g_hist[tid], hist[tid]);
    __threadfence();

    __shared__ int islast;
    if (tid == 0) islast = (atomicAdd(&g_cnt, 1) == HIST_BLOCKS - 1) ? 1 : 0;
    __syncthreads();
    if (!islast) return;
    __threadfence();

    // sigmoid-sum reduce (64 partials, deterministic tree)
    __shared__ double sd[64];
    if (tid < 64) sd[tid] = (double)g_ssum[tid];
    __syncthreads();
#pragma unroll
    for (int o = 32; o > 0; o >>= 1) {
        if (tid < o) sd[tid] += sd[tid + o];
        __syncthreads();
    }

    // entropy + nonzero count over global histogram
    __shared__ float ssum[256];
    __shared__ int   snz[256];
    int h = __ldcg(&g_hist[tid]);
    float hisv = (float)h * (1.0f / (float)HW_);
    ssum[tid] = hisv * (-logf(hisv + 1e-8f));
    snz[tid]  = (h != 0) ? 1 : 0;
    __syncthreads();
#pragma unroll
    for (int o = 128; o > 0; o >>= 1) {
        if (tid < o) {
            ssum[tid] += ssum[tid + o];
            snz[tid]  += snz[tid + o];
        }
        __syncthreads();
    }

    if (tid == 0) {
        float s = (float)(sd[0] / (double)((size_t)B_ * HW_));
        float entro_final = ssum[0] / (float)snz[0];
        out[0] = s + entro_final * 10.0f;
    }
}

// ---------------------------------------------------------------------------
extern "C" void kernel_launch(void* const* d_in, const int* in_sizes, int n_in,
                              void* d_out, int out_size) {
    const float* x = (const float*)d_in[0];
    float* out = (float*)d_out;

    k_init<<<1, 256>>>();
    k_fused<<<NCTA, 512>>>(x);
    k_entrocomb<<<ENTRO_BLOCKS, 256>>>();
    k_histout<<<HIST_BLOCKS, 256>>>(out);
}

// round 13
// speedup vs baseline: 1.6608x; 1.6608x over previous
#include <cuda_runtime.h>
#include <math_constants.h>

// Shapes (fixed): x: [B=32, C=256, H=128, W=128] float32
#define B_   32
#define C_   256
#define BC_  8192    // B*C
#define HW_  16384   // 128*128
#define HW4_ 4096    // HW/4 (float4 groups)

#define POOL_BLOCKS 1184  // 148 SMs x 8 CTAs: exactly one full wave
#define XN_BLOCKS 512     // 32 b * 16 blocks/b
#define ENTRO_BLOCKS 64
#define HIST_BLOCKS  64

// Scratch (device globals — no allocation allowed)
__device__ float g_pooled[B_ * C_];      // 32 KB
__device__ float g_xn[B_ * HW_];         // 2 MB
__device__ float g_ssum[XN_BLOCKS];      // sigmoid partials
__device__ float g_entro[HW_];           // 64 KB
__device__ float g_mm[ENTRO_BLOCKS * 2]; // per-block (min,max)
__device__ int   g_hist[256];

// ---------------------------------------------------------------------------
// K1: pooled[b,c] = mean over HW. Grid-stride over 8192 channels with a
//     1184-block (148 SM x 8 CTA) single full wave: 100% warp-slot fill,
//     no wave transitions. Block 0 zeroes the histogram.
// ---------------------------------------------------------------------------
__global__ void __launch_bounds__(256) k_pool(const float* __restrict__ x) {
    const int tid = threadIdx.x;
    if (blockIdx.x == 0) g_hist[tid] = 0;

    const float4* __restrict__ x4 = reinterpret_cast<const float4*>(x);
    __shared__ float sw[8];

    for (int bc = blockIdx.x; bc < BC_; bc += POOL_BLOCKS) {
        const float4* __restrict__ p = x4 + (size_t)bc * HW4_;

        float s0 = 0.f, s1 = 0.f, s2 = 0.f, s3 = 0.f;
#pragma unroll
        for (int i = 0; i < 4; i++) {
            float4 a = p[tid + (4 * i + 0) * 256];
            float4 b = p[tid + (4 * i + 1) * 256];
            float4 c = p[tid + (4 * i + 2) * 256];
            float4 d = p[tid + (4 * i + 3) * 256];
            s0 += (a.x + a.y) + (a.z + a.w);
            s1 += (b.x + b.y) + (b.z + b.w);
            s2 += (c.x + c.y) + (c.z + c.w);
            s3 += (d.x + d.y) + (d.z + d.w);
        }
        float s = (s0 + s1) + (s2 + s3);
#pragma unroll
        for (int o = 16; o > 0; o >>= 1)
            s += __shfl_down_sync(0xffffffffu, s, o);

        if ((tid & 31) == 0) sw[tid >> 5] = s;
        __syncthreads();
        if (tid == 0) {
            float t = ((sw[0] + sw[1]) + (sw[2] + sw[3]))
                    + ((sw[4] + sw[5]) + (sw[6] + sw[7]));
            g_pooled[bc] = t * (1.0f / (float)HW_);
        }
        __syncthreads();
    }
}

// ---------------------------------------------------------------------------
// K2 (R3 mainloop): xn[b,sp] = (1/C) * sum_c x[b,c,sp] * pooled[b,c]
//     One thread per float4 spatial group; sigmoid partials via shfl + 1 bar.
// ---------------------------------------------------------------------------
__global__ void __launch_bounds__(256) k_xn(const float* __restrict__ x) {
    const int b   = blockIdx.x >> 4;                        // 0..31
    const int grp = ((blockIdx.x & 15) << 8) + threadIdx.x; // 0..4095

    __shared__ float pw[C_];
    pw[threadIdx.x] = g_pooled[b * C_ + threadIdx.x];
    __syncthreads();

    const float4* __restrict__ xp =
        reinterpret_cast<const float4*>(x) + (size_t)b * C_ * HW4_ + grp;

    float ax = 0.0f, ay = 0.0f, az = 0.0f, aw = 0.0f;
#pragma unroll 8
    for (int c = 0; c < C_; c++) {
        float4 v = xp[(size_t)c * HW4_];
        float w = pw[c];
        ax = fmaf(v.x, w, ax);
        ay = fmaf(v.y, w, ay);
        az = fmaf(v.z, w, az);
        aw = fmaf(v.w, w, aw);
    }
    const float inv = 1.0f / (float)C_;
    float4 xn;
    xn.x = ax * inv; xn.y = ay * inv; xn.z = az * inv; xn.w = aw * inv;
    reinterpret_cast<float4*>(g_xn)[(size_t)b * HW4_ + grp] = xn;

    float sg = 1.0f / (1.0f + __expf(-xn.x))
             + 1.0f / (1.0f + __expf(-xn.y))
             + 1.0f / (1.0f + __expf(-xn.z))
             + 1.0f / (1.0f + __expf(-xn.w));
#pragma unroll
    for (int o = 16; o > 0; o >>= 1)
        sg += __shfl_down_sync(0xffffffffu, sg, o);

    __shared__ float sw[8];
    if ((threadIdx.x & 31) == 0) sw[threadIdx.x >> 5] = sg;
    __syncthreads();
    if (threadIdx.x == 0) {
        float t = ((sw[0] + sw[1]) + (sw[2] + sw[3]))
                + ((sw[4] + sw[5]) + (sw[6] + sw[7]));
        g_ssum[blockIdx.x] = t;
    }
}

// ---------------------------------------------------------------------------
// K3: entro[sp] = mean over b of xn[b,sp]; per-block min/max partials.
// ---------------------------------------------------------------------------
__global__ void __launch_bounds__(256) k_entro() {
    const int sp = blockIdx.x * 256 + threadIdx.x;
    float a = 0.0f;
#pragma unroll
    for (int b = 0; b < B_; b++) a += g_xn[(size_t)b * HW_ + sp];
    float v = a * (1.0f / (float)B_);
    g_entro[sp] = v;

    __shared__ float smin[256], smax[256];
    smin[threadIdx.x] = v;
    smax[threadIdx.x] = v;
    __syncthreads();
#pragma unroll
    for (int o = 128; o > 0; o >>= 1) {
        if (threadIdx.x < o) {
            smin[threadIdx.x] = fminf(smin[threadIdx.x], smin[threadIdx.x + o]);
            smax[threadIdx.x] = fmaxf(smax[threadIdx.x], smax[threadIdx.x + o]);
        }
        __syncthreads();
    }
    if (threadIdx.x == 0) {
        g_mm[blockIdx.x * 2 + 0] = smin[0];
        g_mm[blockIdx.x * 2 + 1] = smax[0];
    }
}

// ---------------------------------------------------------------------------
// K4: 64 blocks: reduce min/max partials (redundant, cheap), bin 256 entro
//     elements each into shared histogram, flush to global histogram.
// ---------------------------------------------------------------------------
__global__ void __launch_bounds__(256) k_hist() {
    const int tid = threadIdx.x;

    __shared__ float smin[64], smax[64];
    __shared__ int hist[256];
    hist[tid] = 0;
    if (tid < 64) {
        smin[tid] = g_mm[tid * 2 + 0];
        smax[tid] = g_mm[tid * 2 + 1];
    }
    __syncthreads();
#pragma unroll
    for (int o = 32; o > 0; o >>= 1) {
        if (tid < o) {
            smin[tid] = fminf(smin[tid], smin[tid + o]);
            smax[tid] = fmaxf(smax[tid], smax[tid + o]);
        }
        __syncthreads();
    }
    const float emin = smin[0];
    const float denom = smax[0] - emin;

    float e = (g_entro[blockIdx.x * 256 + tid] - emin) / denom * 255.0f;
    int bin = (int)floorf(e * (256.0f / 255.0f));
    bin = min(max(bin, 0), 255);
    atomicAdd(&hist[bin], 1);
    __syncthreads();

    if (hist[tid] != 0) atomicAdd(&g_hist[tid], hist[tid]);
}

// ---------------------------------------------------------------------------
// K5: entropy over 256 bins + nz, sigmoid-sum reduce (512 partials), output.
// ---------------------------------------------------------------------------
__global__ void __launch_bounds__(256) k_out(float* __restrict__ out) {
    const int tid = threadIdx.x;

    __shared__ double sd[256];
    sd[tid] = (double)g_ssum[tid] + (double)g_ssum[tid + 256];
    __syncthreads();
#pragma unroll
    for (int o = 128; o > 0; o >>= 1) {
        if (tid < o) sd[tid] += sd[tid + o];
        __syncthreads();
    }

    __shared__ float ssum[256];
    __shared__ int   snz[256];
    int h = g_hist[tid];
    float hisv = (float)h * (1.0f / (float)HW_);
    ssum[tid] = hisv * (-logf(hisv + 1e-8f));
    snz[tid]  = (h != 0) ? 1 : 0;
    __syncthreads();
#pragma unroll
    for (int o = 128; o > 0; o >>= 1) {
        if (tid < o) {
            ssum[tid] += ssum[tid + o];
            snz[tid]  += snz[tid + o];
        }
        __syncthreads();
    }

    if (tid == 0) {
        float s = (float)(sd[0] / (double)((size_t)B_ * HW_));
        float entro_final = ssum[0] / (float)snz[0];
        out[0] = s + entro_final * 10.0f;
    }
}

// ---------------------------------------------------------------------------
extern "C" void kernel_launch(void* const* d_in, const int* in_sizes, int n_in,
                              void* d_out, int out_size) {
    const float* x = (const float*)d_in[0];
    float* out = (float*)d_out;

    k_pool<<<POOL_BLOCKS, 256>>>(x);
    k_xn<<<XN_BLOCKS, 256>>>(x);
    k_entro<<<ENTRO_BLOCKS, 256>>>();
    k_hist<<<HIST_BLOCKS, 256>>>();
    k_out<<<1, 256>>>(out);
}

// round 14
// speedup vs baseline: 1.6673x; 1.0040x over previous
#include <cuda_runtime.h>
#include <math_constants.h>

// Shapes (fixed): x: [B=32, C=256, H=128, W=128] float32
#define B_   32
#define C_   256
#define HW_  16384   // 128*128
#define HW4_ 4096    // HW/4 (float4 groups)

#define XN_BLOCKS 512    // 32 b * 16 blocks/b
#define ENTRO_BLOCKS 64
#define HIST_BLOCKS  64

// Scratch (device globals — no allocation allowed)
__device__ float g_pooled[B_ * C_];      // 32 KB
__device__ float g_xn[B_ * HW_];         // 2 MB
__device__ float g_ssum[XN_BLOCKS];      // sigmoid partials
__device__ float g_entro[HW_];           // 64 KB
__device__ float g_mm[ENTRO_BLOCKS * 2]; // per-block (min,max)
__device__ int   g_hist[256];

__device__ __forceinline__ void gds() {
#if defined(__CUDA_ARCH__) && (__CUDA_ARCH__ >= 900)
    cudaGridDependencySynchronize();
#endif
}

// ---------------------------------------------------------------------------
// K1: pooled[b,c] = mean over HW. One block per (b,c) — champion shape.
//     Block 0 zeroes the histogram for this graph replay.
// ---------------------------------------------------------------------------
__global__ void __launch_bounds__(256) k_pool(const float* __restrict__ x) {
    const int tid = threadIdx.x;
    if (blockIdx.x == 0) g_hist[tid] = 0;

    const int bc = blockIdx.x;   // 0..8191
    const float4* __restrict__ p =
        reinterpret_cast<const float4*>(x) + (size_t)bc * HW4_;

    float s0 = 0.f, s1 = 0.f, s2 = 0.f, s3 = 0.f;
#pragma unroll
    for (int i = 0; i < 4; i++) {
        float4 a = p[tid + (4 * i + 0) * 256];
        float4 b = p[tid + (4 * i + 1) * 256];
        float4 c = p[tid + (4 * i + 2) * 256];
        float4 d = p[tid + (4 * i + 3) * 256];
        s0 += (a.x + a.y) + (a.z + a.w);
        s1 += (b.x + b.y) + (b.z + b.w);
        s2 += (c.x + c.y) + (c.z + c.w);
        s3 += (d.x + d.y) + (d.z + d.w);
    }
    float s = (s0 + s1) + (s2 + s3);
#pragma unroll
    for (int o = 16; o > 0; o >>= 1)
        s += __shfl_down_sync(0xffffffffu, s, o);

    __shared__ float sw[8];
    if ((tid & 31) == 0) sw[tid >> 5] = s;
    __syncthreads();
    if (tid == 0) {
        float t = ((sw[0] + sw[1]) + (sw[2] + sw[3]))
                + ((sw[4] + sw[5]) + (sw[6] + sw[7]));
        g_pooled[bc] = t * (1.0f / (float)HW_);
    }
}

// ---------------------------------------------------------------------------
// K2: xn[b,sp] = (1/C) * sum_c x[b,c,sp] * pooled[b,c]  (champion mainloop)
// ---------------------------------------------------------------------------
__global__ void __launch_bounds__(256) k_xn(const float* __restrict__ x) {
    gds();   // wait for k_pool's g_pooled writes

    const int b   = blockIdx.x >> 4;                        // 0..31
    const int grp = ((blockIdx.x & 15) << 8) + threadIdx.x; // 0..4095

    __shared__ float pw[C_];
    pw[threadIdx.x] = g_pooled[b * C_ + threadIdx.x];
    __syncthreads();

    const float4* __restrict__ xp =
        reinterpret_cast<const float4*>(x) + (size_t)b * C_ * HW4_ + grp;

    float ax = 0.0f, ay = 0.0f, az = 0.0f, aw = 0.0f;
#pragma unroll 8
    for (int c = 0; c < C_; c++) {
        float4 v = xp[(size_t)c * HW4_];
        float w = pw[c];
        ax = fmaf(v.x, w, ax);
        ay = fmaf(v.y, w, ay);
        az = fmaf(v.z, w, az);
        aw = fmaf(v.w, w, aw);
    }
    const float inv = 1.0f / (float)C_;
    float4 xn;
    xn.x = ax * inv; xn.y = ay * inv; xn.z = az * inv; xn.w = aw * inv;
    reinterpret_cast<float4*>(g_xn)[(size_t)b * HW4_ + grp] = xn;

    float sg = 1.0f / (1.0f + __expf(-xn.x))
             + 1.0f / (1.0f + __expf(-xn.y))
             + 1.0f / (1.0f + __expf(-xn.z))
             + 1.0f / (1.0f + __expf(-xn.w));
#pragma unroll
    for (int o = 16; o > 0; o >>= 1)
        sg += __shfl_down_sync(0xffffffffu, sg, o);

    __shared__ float sw[8];
    if ((threadIdx.x & 31) == 0) sw[threadIdx.x >> 5] = sg;
    __syncthreads();
    if (threadIdx.x == 0) {
        float t = ((sw[0] + sw[1]) + (sw[2] + sw[3]))
                + ((sw[4] + sw[5]) + (sw[6] + sw[7]));
        g_ssum[blockIdx.x] = t;
    }
}

// ---------------------------------------------------------------------------
// K3: entro[sp] = mean over b of xn[b,sp]; per-block min/max partials.
// ---------------------------------------------------------------------------
__global__ void __launch_bounds__(256) k_entro() {
    gds();   // wait for k_xn's g_xn writes

    const int sp = blockIdx.x * 256 + threadIdx.x;
    float a = 0.0f;
#pragma unroll
    for (int b = 0; b < B_; b++) a += g_xn[(size_t)b * HW_ + sp];
    float v = a * (1.0f / (float)B_);
    g_entro[sp] = v;

    __shared__ float smin[256], smax[256];
    smin[threadIdx.x] = v;
    smax[threadIdx.x] = v;
    __syncthreads();
#pragma unroll
    for (int o = 128; o > 0; o >>= 1) {
        if (threadIdx.x < o) {
            smin[threadIdx.x] = fminf(smin[threadIdx.x], smin[threadIdx.x + o]);
            smax[threadIdx.x] = fmaxf(smax[threadIdx.x], smax[threadIdx.x + o]);
        }
        __syncthreads();
    }
    if (threadIdx.x == 0) {
        g_mm[blockIdx.x * 2 + 0] = smin[0];
        g_mm[blockIdx.x * 2 + 1] = smax[0];
    }
}

// ---------------------------------------------------------------------------
// K4: 64 blocks: reduce min/max partials (redundant, cheap), bin 256 entro
//     elements each into shared histogram, flush to global histogram.
// ---------------------------------------------------------------------------
__global__ void __launch_bounds__(256) k_hist() {
    gds();   // wait for k_entro's g_entro / g_mm writes

    const int tid = threadIdx.x;

    __shared__ float smin[64], smax[64];
    __shared__ int hist[256];
    hist[tid] = 0;
    if (tid < 64) {
        smin[tid] = g_mm[tid * 2 + 0];
        smax[tid] = g_mm[tid * 2 + 1];
    }
    __syncthreads();
#pragma unroll
    for (int o = 32; o > 0; o >>= 1) {
        if (tid < o) {
            smin[tid] = fminf(smin[tid], smin[tid + o]);
            smax[tid] = fmaxf(smax[tid], smax[tid + o]);
        }
        __syncthreads();
    }
    const float emin = smin[0];
    const float denom = smax[0] - emin;

    float e = (g_entro[blockIdx.x * 256 + tid] - emin) / denom * 255.0f;
    int bin = (int)floorf(e * (256.0f / 255.0f));
    bin = min(max(bin, 0), 255);
    atomicAdd(&hist[bin], 1);
    __syncthreads();

    if (hist[tid] != 0) atomicAdd(&g_hist[tid], hist[tid]);
}

// ---------------------------------------------------------------------------
// K5: entropy over 256 bins + nz, sigmoid-sum reduce (512 partials), output.
// ---------------------------------------------------------------------------
__global__ void __launch_bounds__(256) k_out(float* __restrict__ out) {
    gds();   // wait for k_hist's g_hist writes

    const int tid = threadIdx.x;

    __shared__ double sd[256];
    sd[tid] = (double)g_ssum[tid] + (double)g_ssum[tid + 256];
    __syncthreads();
#pragma unroll
    for (int o = 128; o > 0; o >>= 1) {
        if (tid < o) sd[tid] += sd[tid + o];
        __syncthreads();
    }

    __shared__ float ssum[256];
    __shared__ int   snz[256];
    int h = g_hist[tid];
    float hisv = (float)h * (1.0f / (float)HW_);
    ssum[tid] = hisv * (-logf(hisv + 1e-8f));
    snz[tid]  = (h != 0) ? 1 : 0;
    __syncthreads();
#pragma unroll
    for (int o = 128; o > 0; o >>= 1) {
        if (tid < o) {
            ssum[tid] += ssum[tid + o];
            snz[tid]  += snz[tid + o];
        }
        __syncthreads();
    }

    if (tid == 0) {
        float s = (float)(sd[0] / (double)((size_t)B_ * HW_));
        float entro_final = ssum[0] / (float)snz[0];
        out[0] = s + entro_final * 10.0f;
    }
}

// ---------------------------------------------------------------------------
// Launch: k_pool normally; all downstream kernels via PDL so their launch
// latency overlaps the predecessor's tail. Kernel bodies unchanged from the
// 162.3us champion.
// ---------------------------------------------------------------------------
static inline void launch_pdl(void* func, dim3 grid, dim3 block,
                              void** args) {
    cudaLaunchConfig_t cfg = {};
    cfg.gridDim  = grid;
    cfg.blockDim = block;
    cfg.dynamicSmemBytes = 0;
    cfg.stream = 0;   // legacy default stream (same as <<<>>>)
    cudaLaunchAttribute attr[1];
    attr[0].id = cudaLaunchAttributeProgrammaticStreamSerialization;
    attr[0].val.programmaticStreamSerializationAllowed = 1;
    cfg.attrs = attr;
    cfg.numAttrs = 1;
    cudaLaunchKernelExC(&cfg, func, args);
}

extern "C" void kernel_launch(void* const* d_in, const int* in_sizes, int n_in,
                              void* d_out, int out_size) {
    const float* x = (const float*)d_in[0];
    float* out = (float*)d_out;

    k_pool<<<B_ * C_, 256>>>(x);

    {   // k_xn(x)
        void* args[] = { (void*)&x };
        launch_pdl((void*)k_xn, dim3(XN_BLOCKS), dim3(256), args);
    }
    {   // k_entro()
        launch_pdl((void*)k_entro, dim3(ENTRO_BLOCKS), dim3(256), nullptr);
    }
    {   // k_hist()
        launch_pdl((void*)k_hist, dim3(HIST_BLOCKS), dim3(256), nullptr);
    }
    {   // k_out(out)
        void* args[] = { (void*)&out };
        launch_pdl((void*)k_out, dim3(1), dim3(256), args);
    }
}

// round 15
// speedup vs baseline: 1.6756x; 1.0050x over previous
#include <cuda_runtime.h>
#include <math_constants.h>

// Shapes (fixed): x: [B=32, C=256, H=128, W=128] float32
#define B_   32
#define C_   256
#define HW_  16384   // 128*128
#define HW4_ 4096    // HW/4 (float4 groups)

#define XN_BLOCKS 512    // 32 b * 16 blocks/b
#define ENTRO_BLOCKS 64
#define HIST_BLOCKS  64

// Scratch (device globals — no allocation allowed)
__device__ float g_pooled[B_ * C_];      // 32 KB
__device__ float g_xn[B_ * HW_];         // 2 MB
__device__ float g_ssum[XN_BLOCKS];      // sigmoid partials
__device__ float g_entro[HW_];           // 64 KB
__device__ float g_mm[ENTRO_BLOCKS * 2]; // per-block (min,max)
__device__ int   g_hist[256];

__device__ __forceinline__ void gds() {
#if defined(__CUDA_ARCH__) && (__CUDA_ARCH__ >= 900)
    cudaGridDependencySynchronize();
#endif
}

// ---------------------------------------------------------------------------
// K1: pooled[b,c] = mean over HW. One block per (b,c).
//     2 iterations x 8 front-batched float4 loads, 8 independent accumulators
//     (front-batch depth 8 vs 4 -> higher MLP_eff, regs stay occ-8 safe).
//     Block 0 zeroes the histogram for this graph replay.
// ---------------------------------------------------------------------------
__global__ void __launch_bounds__(256) k_pool(const float* __restrict__ x) {
    const int tid = threadIdx.x;
    if (blockIdx.x == 0) g_hist[tid] = 0;

    const int bc = blockIdx.x;   // 0..8191
    const float4* __restrict__ p =
        reinterpret_cast<const float4*>(x) + (size_t)bc * HW4_;

    float s0 = 0.f, s1 = 0.f, s2 = 0.f, s3 = 0.f;
    float s4 = 0.f, s5 = 0.f, s6 = 0.f, s7 = 0.f;
#pragma unroll
    for (int i = 0; i < 2; i++) {
        float4 a = p[tid + (8 * i + 0) * 256];
        float4 b = p[tid + (8 * i + 1) * 256];
        float4 c = p[tid + (8 * i + 2) * 256];
        float4 d = p[tid + (8 * i + 3) * 256];
        float4 e = p[tid + (8 * i + 4) * 256];
        float4 f = p[tid + (8 * i + 5) * 256];
        float4 g = p[tid + (8 * i + 6) * 256];
        float4 h = p[tid + (8 * i + 7) * 256];
        s0 += (a.x + a.y) + (a.z + a.w);
        s1 += (b.x + b.y) + (b.z + b.w);
        s2 += (c.x + c.y) + (c.z + c.w);
        s3 += (d.x + d.y) + (d.z + d.w);
        s4 += (e.x + e.y) + (e.z + e.w);
        s5 += (f.x + f.y) + (f.z + f.w);
        s6 += (g.x + g.y) + (g.z + g.w);
        s7 += (h.x + h.y) + (h.z + h.w);
    }
    float s = (((s0 + s1) + (s2 + s3)) + ((s4 + s5) + (s6 + s7)));
#pragma unroll
    for (int o = 16; o > 0; o >>= 1)
        s += __shfl_down_sync(0xffffffffu, s, o);

    __shared__ float sw[8];
    if ((tid & 31) == 0) sw[tid >> 5] = s;
    __syncthreads();
    if (tid == 0) {
        float t = ((sw[0] + sw[1]) + (sw[2] + sw[3]))
                + ((sw[4] + sw[5]) + (sw[6] + sw[7]));
        g_pooled[bc] = t * (1.0f / (float)HW_);
    }
}

// ---------------------------------------------------------------------------
// K2: xn[b,sp] = (1/C) * sum_c x[b,c,sp] * pooled[b,c]   (unroll 8 -> 16)
// ---------------------------------------------------------------------------
__global__ void __launch_bounds__(256) k_xn(const float* __restrict__ x) {
    gds();   // wait for k_pool's g_pooled writes

    const int b   = blockIdx.x >> 4;                        // 0..31
    const int grp = ((blockIdx.x & 15) << 8) + threadIdx.x; // 0..4095

    __shared__ float pw[C_];
    pw[threadIdx.x] = g_pooled[b * C_ + threadIdx.x];
    __syncthreads();

    const float4* __restrict__ xp =
        reinterpret_cast<const float4*>(x) + (size_t)b * C_ * HW4_ + grp;

    float ax = 0.0f, ay = 0.0f, az = 0.0f, aw = 0.0f;
#pragma unroll 16
    for (int c = 0; c < C_; c++) {
        float4 v = xp[(size_t)c * HW4_];
        float w = pw[c];
        ax = fmaf(v.x, w, ax);
        ay = fmaf(v.y, w, ay);
        az = fmaf(v.z, w, az);
        aw = fmaf(v.w, w, aw);
    }
    const float inv = 1.0f / (float)C_;
    float4 xn;
    xn.x = ax * inv; xn.y = ay * inv; xn.z = az * inv; xn.w = aw * inv;
    reinterpret_cast<float4*>(g_xn)[(size_t)b * HW4_ + grp] = xn;

    float sg = 1.0f / (1.0f + __expf(-xn.x))
             + 1.0f / (1.0f + __expf(-xn.y))
             + 1.0f / (1.0f + __expf(-xn.z))
             + 1.0f / (1.0f + __expf(-xn.w));
#pragma unroll
    for (int o = 16; o > 0; o >>= 1)
        sg += __shfl_down_sync(0xffffffffu, sg, o);

    __shared__ float sw[8];
    if ((threadIdx.x & 31) == 0) sw[threadIdx.x >> 5] = sg;
    __syncthreads();
    if (threadIdx.x == 0) {
        float t = ((sw[0] + sw[1]) + (sw[2] + sw[3]))
                + ((sw[4] + sw[5]) + (sw[6] + sw[7]));
        g_ssum[blockIdx.x] = t;
    }
}

// ---------------------------------------------------------------------------
// K3: entro[sp] = mean over b of xn[b,sp]; per-block min/max partials.
// ---------------------------------------------------------------------------
__global__ void __launch_bounds__(256) k_entro() {
    gds();   // wait for k_xn's g_xn writes

    const int sp = blockIdx.x * 256 + threadIdx.x;
    float a = 0.0f;
#pragma unroll
    for (int b = 0; b < B_; b++) a += g_xn[(size_t)b * HW_ + sp];
    float v = a * (1.0f / (float)B_);
    g_entro[sp] = v;

    __shared__ float smin[256], smax[256];
    smin[threadIdx.x] = v;
    smax[threadIdx.x] = v;
    __syncthreads();
#pragma unroll
    for (int o = 128; o > 0; o >>= 1) {
        if (threadIdx.x < o) {
            smin[threadIdx.x] = fminf(smin[threadIdx.x], smin[threadIdx.x + o]);
            smax[threadIdx.x] = fmaxf(smax[threadIdx.x], smax[threadIdx.x + o]);
        }
        __syncthreads();
    }
    if (threadIdx.x == 0) {
        g_mm[blockIdx.x * 2 + 0] = smin[0];
        g_mm[blockIdx.x * 2 + 1] = smax[0];
    }
}

// ---------------------------------------------------------------------------
// K4: 64 blocks: reduce min/max partials (redundant, cheap), bin 256 entro
//     elements each into shared histogram, flush to global histogram.
// ---------------------------------------------------------------------------
__global__ void __launch_bounds__(256) k_hist() {
    gds();   // wait for k_entro's g_entro / g_mm writes

    const int tid = threadIdx.x;

    __shared__ float smin[64], smax[64];
    __shared__ int hist[256];
    hist[tid] = 0;
    if (tid < 64) {
        smin[tid] = g_mm[tid * 2 + 0];
        smax[tid] = g_mm[tid * 2 + 1];
    }
    __syncthreads();
#pragma unroll
    for (int o = 32; o > 0; o >>= 1) {
        if (tid < o) {
            smin[tid] = fminf(smin[tid], smin[tid + o]);
            smax[tid] = fmaxf(smax[tid], smax[tid + o]);
        }
        __syncthreads();
    }
    const float emin = smin[0];
    const float denom = smax[0] - emin;

    float e = (g_entro[blockIdx.x * 256 + tid] - emin) / denom * 255.0f;
    int bin = (int)floorf(e * (256.0f / 255.0f));
    bin = min(max(bin, 0), 255);
    atomicAdd(&hist[bin], 1);
    __syncthreads();

    if (hist[tid] != 0) atomicAdd(&g_hist[tid], hist[tid]);
}

// ---------------------------------------------------------------------------
// K5: entropy over 256 bins + nz, sigmoid-sum reduce (512 partials), output.
// ---------------------------------------------------------------------------
__global__ void __launch_bounds__(256) k_out(float* __restrict__ out) {
    gds();   // wait for k_hist's g_hist writes

    const int tid = threadIdx.x;

    __shared__ double sd[256];
    sd[tid] = (double)g_ssum[tid] + (double)g_ssum[tid + 256];
    __syncthreads();
#pragma unroll
    for (int o = 128; o > 0; o >>= 1) {
        if (tid < o) sd[tid] += sd[tid + o];
        __syncthreads();
    }

    __shared__ float ssum[256];
    __shared__ int   snz[256];
    int h = g_hist[tid];
    float hisv = (float)h * (1.0f / (float)HW_);
    ssum[tid] = hisv * (-logf(hisv + 1e-8f));
    snz[tid]  = (h != 0) ? 1 : 0;
    __syncthreads();
#pragma unroll
    for (int o = 128; o > 0; o >>= 1) {
        if (tid < o) {
            ssum[tid] += ssum[tid + o];
            snz[tid]  += snz[tid + o];
        }
        __syncthreads();
    }

    if (tid == 0) {
        float s = (float)(sd[0] / (double)((size_t)B_ * HW_));
        float entro_final = ssum[0] / (float)snz[0];
        out[0] = s + entro_final * 10.0f;
    }
}

// ---------------------------------------------------------------------------
// Launch: k_pool normally; downstream kernels via PDL (champion launch path).
// ---------------------------------------------------------------------------
static inline void launch_pdl(void* func, dim3 grid, dim3 block,
                              void** args) {
    cudaLaunchConfig_t cfg = {};
    cfg.gridDim  = grid;
    cfg.blockDim = block;
    cfg.dynamicSmemBytes = 0;
    cfg.stream = 0;   // legacy default stream (same as <<<>>>)
    cudaLaunchAttribute attr[1];
    attr[0].id = cudaLaunchAttributeProgrammaticStreamSerialization;
    attr[0].val.programmaticStreamSerializationAllowed = 1;
    cfg.attrs = attr;
    cfg.numAttrs = 1;
    cudaLaunchKernelExC(&cfg, func, args);
}

extern "C" void kernel_launch(void* const* d_in, const int* in_sizes, int n_in,
                              void* d_out, int out_size) {
    const float* x = (const float*)d_in[0];
    float* out = (float*)d_out;

    k_pool<<<B_ * C_, 256>>>(x);

    {   // k_xn(x)
        void* args[] = { (void*)&x };
        launch_pdl((void*)k_xn, dim3(XN_BLOCKS), dim3(256), args);
    }
    {   // k_entro()
        launch_pdl((void*)k_entro, dim3(ENTRO_BLOCKS), dim3(256), nullptr);
    }
    {   // k_hist()
        launch_pdl((void*)k_hist, dim3(HIST_BLOCKS), dim3(256), nullptr);
    }
    {   // k_out(out)
        void* args[] = { (void*)&out };
        launch_pdl((void*)k_out, dim3(1), dim3(256), args);
    }
}